// round 16
// baseline (speedup 1.0000x reference)
#include <cuda_runtime.h>
#include <cuda_bf16.h>
#include <cstdint>

// NV12 -> RGB, 4K frame. R2 access shape (2 px/thread, warp-contiguous
// 16B-stride int4 loads, 3x float2 stores), instruction-lean version:
//  - matrix + offset in __constant__ memory (48B cudaMemcpyToSymbolAsync,
//    D2D, graph-capturable) -> removes 12 uniform LDGs/thread (over half of
//    all L1 load wavefronts) in favor of constant-bank immediates.
//  - 2D grid (blockIdx.y = row) -> removes the idx/1920 division.
//  - L2 policy: UV evict_last, Y/output evict_first (free; small traffic cut).
// d_in[0]: int32 flattened: [0 : 7680*4320) full-res Y, then (2160,3840,2) UV.
// d_in[1]: float32[9] yuv_to_rgb (row-major 3x3), d_in[2]: float32[3] offset.
// out: float32 (2160, 3840, 3): rgb[j] = sum_i (yuv[i]-off[i]) * M[i][j],
// yuv = [Y[2r,2c], U[r,c], V[r,c]].

#define HH 2160
#define HW 3840
#define FULL_W (HW * 2)            // 7680
#define Y_ELEMS (FULL_W * HH * 2)  // 33177600
#define PPR (HW / 2)               // 1920 pairs per row
#define NTHREADS 384               // 384 * 5 = 1920: exact row coverage
#define BPR 5                      // blocks per row

__constant__ float cM[9];
__constant__ float cOff[3];

__device__ __forceinline__ int4 ldg_hint_int4(const int* p, uint64_t pol)
{
    int4 v;
    asm volatile("ld.global.nc.L2::cache_hint.v4.u32 {%0,%1,%2,%3}, [%4], %5;"
                 : "=r"(v.x), "=r"(v.y), "=r"(v.z), "=r"(v.w)
                 : "l"(p), "l"(pol));
    return v;
}

__device__ __forceinline__ void stg_hint_f2(float* p, float a, float b, uint64_t pol)
{
    asm volatile("st.global.L2::cache_hint.v2.f32 [%0], {%1,%2}, %3;"
                 :: "l"(p), "f"(a), "f"(b), "l"(pol)
                 : "memory");
}

__global__ __launch_bounds__(NTHREADS)
void nv12_to_rgb_kernel(const int* __restrict__ data,
                        float* __restrict__ out)
{
    uint64_t pol_keep, pol_stream;
    asm volatile("createpolicy.fractional.L2::evict_last.b64 %0, 1.0;"  : "=l"(pol_keep));
    asm volatile("createpolicy.fractional.L2::evict_first.b64 %0, 1.0;" : "=l"(pol_stream));

    const int r = blockIdx.y;                                // half-res row
    const int c = (blockIdx.x * NTHREADS + threadIdx.x) * 2; // even half-res col

    // Warp-contiguous, 16B thread stride: 512B contiguous per warp per LDG.
    const int4 yv = ldg_hint_int4(data + (2 * r) * FULL_W + 2 * c, pol_stream);
    const int4 uv = ldg_hint_int4(data + Y_ELEMS + (r * HW + c) * 2, pol_keep);

    // Constants come from the constant bank (immediate operands, no L1 traffic).
    const float ya = (float)yv.x - cOff[0], yb = (float)yv.z - cOff[0];
    const float ua = (float)uv.x - cOff[1], ub = (float)uv.z - cOff[1];
    const float va = (float)uv.y - cOff[2], vb = (float)uv.w - cOff[2];

    const float r0 = ya * cM[0] + ua * cM[3] + va * cM[6];
    const float g0 = ya * cM[1] + ua * cM[4] + va * cM[7];
    const float b0 = ya * cM[2] + ua * cM[5] + va * cM[8];
    const float r1 = yb * cM[0] + ub * cM[3] + vb * cM[6];
    const float g1 = yb * cM[1] + ub * cM[4] + vb * cM[7];
    const float b1 = yb * cM[2] + ub * cM[5] + vb * cM[8];

    float* o = out + (r * HW + c) * 3;  // 8B-aligned (c even)
    stg_hint_f2(o + 0, r0, g0, pol_stream);
    stg_hint_f2(o + 2, b0, r1, pol_stream);
    stg_hint_f2(o + 4, g1, b1, pol_stream);
}

extern "C" void kernel_launch(void* const* d_in, const int* in_sizes, int n_in,
                              void* d_out, int out_size)
{
    const int*   data = (const int*)d_in[0];
    float*       out  = (float*)d_out;

    // 48B device->constant copies; async + graph-capturable.
    cudaMemcpyToSymbolAsync(cM,   d_in[1], 9 * sizeof(float), 0,
                            cudaMemcpyDeviceToDevice);
    cudaMemcpyToSymbolAsync(cOff, d_in[2], 3 * sizeof(float), 0,
                            cudaMemcpyDeviceToDevice);

    dim3 grid(BPR, HH);  // 5 x 2160 blocks, exact coverage, no tail
    nv12_to_rgb_kernel<<<grid, NTHREADS>>>(data, out);
}

// round 17
// speedup vs baseline: 1.0906x; 1.0906x over previous
#include <cuda_runtime.h>
#include <cuda_bf16.h>
#include <cstdint>

// NV12 -> RGB, 4K frame. Final converged kernel:
//  - R2 access shape: 2 px/thread, warp-contiguous 16B-stride int4 loads,
//    3x float2 stores (every deviation measured slower: R3 v4x2, R4 far-MLP,
//    R5 smem stores, R8 persistent, R9 v8.b32, R10 TMA all >= this).
//  - R15 lean body: 2D grid (blockIdx.y = row, no integer division),
//    384 threads x 5 blocks/row exact coverage, ~18 regs.
//  - R12 policy (session-best kernel time 30.9us): inputs evict_last,
//    output evict_first.
//  - constants via __ldg kernel args: zero extra graph nodes (R15's
//    cudaMemcpyToSymbolAsync cost +3us of replay overhead).
// Kernel is at the mixed-R/W DRAM service floor (~177MB @ ~5.7TB/s).
// d_in[0]: int32 flattened: [0 : 7680*4320) full-res Y, then (2160,3840,2) UV.
// d_in[1]: float32[9] yuv_to_rgb (row-major 3x3), d_in[2]: float32[3] offset.
// out: float32 (2160, 3840, 3): rgb[j] = sum_i (yuv[i]-off[i]) * M[i][j],
// yuv = [Y[2r,2c], U[r,c], V[r,c]].

#define HH 2160
#define HW 3840
#define FULL_W (HW * 2)            // 7680
#define Y_ELEMS (FULL_W * HH * 2)  // 33177600
#define NTHREADS 384               // 384 * 5 = 1920 pairs: exact row coverage
#define BPR 5                      // blocks per row

__device__ __forceinline__ int4 ldg_hint_int4(const int* p, uint64_t pol)
{
    int4 v;
    asm volatile("ld.global.nc.L2::cache_hint.v4.u32 {%0,%1,%2,%3}, [%4], %5;"
                 : "=r"(v.x), "=r"(v.y), "=r"(v.z), "=r"(v.w)
                 : "l"(p), "l"(pol));
    return v;
}

__device__ __forceinline__ void stg_hint_f2(float* p, float a, float b, uint64_t pol)
{
    asm volatile("st.global.L2::cache_hint.v2.f32 [%0], {%1,%2}, %3;"
                 :: "l"(p), "f"(a), "f"(b), "l"(pol)
                 : "memory");
}

__global__ __launch_bounds__(NTHREADS)
void nv12_to_rgb_kernel(const int* __restrict__ data,
                        const float* __restrict__ M,
                        const float* __restrict__ off,
                        float* __restrict__ out)
{
    uint64_t pol_keep, pol_stream;
    asm volatile("createpolicy.fractional.L2::evict_last.b64 %0, 1.0;"  : "=l"(pol_keep));
    asm volatile("createpolicy.fractional.L2::evict_first.b64 %0, 1.0;" : "=l"(pol_stream));

    const int r = blockIdx.y;                                 // half-res row
    const int c = (blockIdx.x * NTHREADS + threadIdx.x) * 2;  // even half-res col

    // Warp-contiguous, 16B thread stride: 512B contiguous per warp per LDG.
    const int4 yv = ldg_hint_int4(data + (2 * r) * FULL_W + 2 * c, pol_keep);
    const int4 uv = ldg_hint_int4(data + Y_ELEMS + (r * HW + c) * 2, pol_keep);

    // Matrix + offset: uniform addresses -> L1 broadcast, hoisted once.
    const float m00 = __ldg(M + 0), m01 = __ldg(M + 1), m02 = __ldg(M + 2);
    const float m10 = __ldg(M + 3), m11 = __ldg(M + 4), m12 = __ldg(M + 5);
    const float m20 = __ldg(M + 6), m21 = __ldg(M + 7), m22 = __ldg(M + 8);
    const float o0 = __ldg(off + 0), o1 = __ldg(off + 1), o2 = __ldg(off + 2);

    const float ya = (float)yv.x - o0, yb = (float)yv.z - o0;
    const float ua = (float)uv.x - o1, ub = (float)uv.z - o1;
    const float va = (float)uv.y - o2, vb = (float)uv.w - o2;

    const float r0 = ya * m00 + ua * m10 + va * m20;
    const float g0 = ya * m01 + ua * m11 + va * m21;
    const float b0 = ya * m02 + ua * m12 + va * m22;
    const float r1 = yb * m00 + ub * m10 + vb * m20;
    const float g1 = yb * m01 + ub * m11 + vb * m21;
    const float b1 = yb * m02 + ub * m12 + vb * m22;

    float* o = out + (r * HW + c) * 3;  // 8B-aligned (c even)
    stg_hint_f2(o + 0, r0, g0, pol_stream);
    stg_hint_f2(o + 2, b0, r1, pol_stream);
    stg_hint_f2(o + 4, g1, b1, pol_stream);
}

extern "C" void kernel_launch(void* const* d_in, const int* in_sizes, int n_in,
                              void* d_out, int out_size)
{
    const int*   data = (const int*)d_in[0];
    const float* M    = (const float*)d_in[1];
    const float* off  = (const float*)d_in[2];
    float*       out  = (float*)d_out;

    dim3 grid(BPR, HH);  // 5 x 2160 blocks, exact coverage, no tail
    nv12_to_rgb_kernel<<<grid, NTHREADS>>>(data, M, off, out);
}